// round 3
// baseline (speedup 1.0000x reference)
#include <cuda_runtime.h>
#include <math.h>

#define D_     32
#define H_     56
#define W_     56
#define HW     3136        // 56*56
#define P_     100352      // 32*56*56
#define CIN    64
#define HID    128
#define DIN    256
#define NST    16
#define L_     32

// ---------------- f32x2 helpers (FFMA2 — only reachable via PTX) -----------
__device__ __forceinline__ void fma2(unsigned long long& d,
                                     unsigned long long a,
                                     unsigned long long b) {
    asm("fma.rn.f32x2 %0, %1, %2, %0;" : "+l"(d) : "l"(a), "l"(b));
}
__device__ __forceinline__ unsigned long long dup2(float x) {
    unsigned long long r;
    asm("mov.b64 %0, {%1, %1};" : "=l"(r) : "f"(x));
    return r;
}
__device__ __forceinline__ float2 unpk(unsigned long long v) {
    float2 f;
    asm("mov.b64 {%0, %1}, %2;" : "=f"(f.x), "=f"(f.y) : "l"(v));
    return f;
}

// ---------------- scratch (static device memory; no allocs allowed) --------
__device__ float g_x   [2 * 256 * P_];        // pointwise-conv output (2,256,D,H,W)
__device__ float g_xc  [2 * 256 * P_];        // depthwise-conv output
__device__ float g_x1r [2 * 128 * P_];        // relu(dense conv) of x1 half
__device__ float g_wt  [27 * 128 * 128];      // W_s transposed to [tap][c][o]
__device__ float g_t0  [2 * 128 * L_];        // pooled x2: [b][c][d]
__device__ float g_gate[2 * 128 * L_];        // sigmoid gate: [b][o][l]

// ---------------- K0: transpose dense-conv weights to [tap][c][o] ----------
__global__ void k_wt(const float* __restrict__ Ws) {
    int i = blockIdx.x * 256 + threadIdx.x;
    if (i >= 27 * 128 * 128) return;
    int tap = i / (128 * 128);
    int r   = i % (128 * 128);
    int c   = r / 128;
    int o   = r % 128;
    g_wt[i] = Ws[(o * 128 + c) * 27 + tap];
}

// ---------------- K1: pointwise conv 64 -> 256 (f32x2) ---------------------
// grid (784, 2), 256 thr. smem: Wsh [c][256] (64KB) + Ish [64][128] (32KB)
__global__ void __launch_bounds__(256) k_pw(const float* __restrict__ inp,
                                            const float* __restrict__ Win) {
    extern __shared__ float sm[];
    float* Wsh = sm;            // 16384 floats: [c*256 + o]
    float* Ish = sm + 16384;    //  8192 floats: [c*128 + p]
    int b  = blockIdx.y;
    int p0 = blockIdx.x * 128;
    int tid = threadIdx.x;
    for (int i = tid; i < 16384; i += 256) {
        int o = i >> 6, c = i & 63;
        Wsh[c * 256 + o] = Win[i];
    }
    for (int i = tid; i < 8192; i += 256) {
        int c = i >> 7, p = i & 127;
        Ish[i] = inp[(size_t)(b * 64 + c) * P_ + p0 + p];
    }
    __syncthreads();
    int p  = tid & 127;
    int oh = tid >> 7;              // 0..1: o half
    size_t base = (size_t)(b * 256) * P_ + p0 + p;
    for (int oc = 0; oc < 8; oc++) {
        int ob = oh * 128 + oc * 16;
        unsigned long long acc[8];
        #pragma unroll
        for (int j = 0; j < 8; j++) acc[j] = 0ull;
        #pragma unroll 8
        for (int c = 0; c < 64; c++) {
            unsigned long long xx = dup2(Ish[c * 128 + p]);
            const ulonglong2* wp = (const ulonglong2*)&Wsh[c * 256 + ob];
            ulonglong2 w0 = wp[0], w1 = wp[1], w2 = wp[2], w3 = wp[3];
            fma2(acc[0], w0.x, xx); fma2(acc[1], w0.y, xx);
            fma2(acc[2], w1.x, xx); fma2(acc[3], w1.y, xx);
            fma2(acc[4], w2.x, xx); fma2(acc[5], w2.y, xx);
            fma2(acc[6], w3.x, xx); fma2(acc[7], w3.y, xx);
        }
        #pragma unroll
        for (int j = 0; j < 8; j++) {
            float2 f = unpk(acc[j]);
            g_x[base + (size_t)(ob + 2 * j)     * P_] = f.x;
            g_x[base + (size_t)(ob + 2 * j + 1) * P_] = f.y;
        }
    }
}

// ---------------- K2: depthwise 3x3x3 with rolling planes + fused pool -----
// grid 512 = b*256 channels, 256 thr. Each block: one (b,c), loops d.
__global__ void __launch_bounds__(256) k_dw(const float* __restrict__ Wdw) {
    __shared__ float buf[3][HW];
    __shared__ float red[8];
    int blk = blockIdx.x;
    int b = blk >> 8, c = blk & 255;
    int tid = threadIdx.x;
    int lane = tid & 31, wid = tid >> 5;
    float wreg[27];
    #pragma unroll
    for (int t = 0; t < 27; t++) wreg[t] = Wdw[c * 27 + t];
    const float* src = &g_x [(size_t)(b * 256 + c) * P_];
    float*       dst = &g_xc[(size_t)(b * 256 + c) * P_];
    bool pool = (c >= 128);

    for (int i = tid; i < HW; i += 256) buf[0][i] = src[i];

    for (int d = 0; d < D_; d++) {
        __syncthreads();           // plane (d+1)%3 free to overwrite
        if (d + 1 < D_) {
            float* nb = buf[(d + 1) % 3];
            const float* np = &src[(d + 1) * HW];
            for (int i = tid; i < HW; i += 256) nb[i] = np[i];
        }
        __syncthreads();
        const float* pm1 = (d > 0)      ? buf[(d + 2) % 3] : nullptr;
        const float* p0  =                buf[d % 3];
        const float* pp1 = (d + 1 < D_) ? buf[(d + 1) % 3] : nullptr;
        const float* pl[3] = {pm1, p0, pp1};
        float psum = 0.f;
        for (int i = tid; i < HW; i += 256) {
            int h = i / 56, w = i % 56;
            float acc = 0.f;
            #pragma unroll
            for (int kd = 0; kd < 3; kd++) {
                const float* pn = pl[kd];
                if (!pn) continue;
                #pragma unroll
                for (int kh = 0; kh < 3; kh++) {
                    int hh = h + kh - 1;
                    if ((unsigned)hh >= 56u) continue;
                    const float* row = &pn[hh * 56];
                    #pragma unroll
                    for (int kw = 0; kw < 3; kw++) {
                        int ww = w + kw - 1;
                        if ((unsigned)ww < 56u)
                            acc += wreg[kd * 9 + kh * 3 + kw] * row[ww];
                    }
                }
            }
            dst[d * HW + i] = acc;
            psum += acc;
        }
        if (pool) {
            #pragma unroll
            for (int off = 16; off; off >>= 1)
                psum += __shfl_down_sync(0xffffffffu, psum, off);
            if (lane == 0) red[wid] = psum;
            __syncthreads();
            if (tid == 0) {
                float s = 0.f;
                #pragma unroll
                for (int j = 0; j < 8; j++) s += red[j];
                g_t0[(b * 128 + (c - 128)) * L_ + d] = s * (1.f / 3136.f);
            }
        }
    }
}

// ---------------- K3: dense 3x3x3 conv 128->128 + relu (f32x2) -------------
// grid (28, 32, 2): block = (b, d, 2 h-rows) x all o x all w. 256 thr, 184KB.
// Thread: o=8 (og=tid&15), (w=7, h=1) tile (grp=tid>>4: wg=grp&7, hh2=grp>>3).
__global__ void __launch_bounds__(256, 1) k_conv() {
    extern __shared__ float sm[];
    float* Ish = sm;            // 4*128*58 = 29696 floats: [row][c][wp]
    float* Wsh = sm + 29696;    // 16384 floats: [c*128 + o]
    int b  = blockIdx.z;
    int d  = blockIdx.y;
    int h0 = blockIdx.x * 2;
    int tid = threadIdx.x;
    int og  = tid & 15;          // o = og*8 + 0..7
    int grp = tid >> 4;
    int wg  = grp & 7;           // w = wg*7 + 0..6
    int hh2 = grp >> 3;          // 0..1
    int ob  = og * 8;
    int wb  = wg * 7;

    unsigned long long acc2[28];
    #pragma unroll
    for (int i = 0; i < 28; i++) acc2[i] = 0ull;

    for (int kd = 0; kd < 3; kd++) {
        int dd = d + kd - 1;
        __syncthreads();   // previous tap finished reading Ish
        for (int i = tid; i < 29696; i += 256) {
            int r   = i / 7424;          // 128*58
            int rem = i % 7424;
            int c   = rem / 58;
            int wp  = rem % 58;
            int hh  = h0 - 1 + r;
            int w   = wp - 1;
            float v = 0.f;
            if (dd >= 0 && dd < D_ && hh >= 0 && hh < 56 && (unsigned)w < 56u)
                v = g_xc[((size_t)(b * 256 + c) * D_ + dd) * HW + hh * 56 + w];
            Ish[i] = v;
        }
        for (int kh = 0; kh < 3; kh++)
        for (int kw = 0; kw < 3; kw++) {
            int tap = (kd * 3 + kh) * 3 + kw;
            __syncthreads();   // Ish stores visible / previous Wsh reads done
            for (int i = tid; i < 16384; i += 256)
                Wsh[i] = g_wt[tap * 16384 + i];
            __syncthreads();
            #pragma unroll 4
            for (int c = 0; c < 128; c++) {
                const ulonglong2* wp2 = (const ulonglong2*)&Wsh[c * 128 + ob];
                ulonglong2 wa = wp2[0];     // o+0..3
                ulonglong2 wb2 = wp2[1];    // o+4..7
                const float* row = &Ish[((hh2 + kh) * 128 + c) * 58 + wb + kw];
                #pragma unroll
                for (int wi = 0; wi < 7; wi++) {
                    unsigned long long xx = dup2(row[wi]);
                    fma2(acc2[wi * 4 + 0], wa.x,  xx);
                    fma2(acc2[wi * 4 + 1], wa.y,  xx);
                    fma2(acc2[wi * 4 + 2], wb2.x, xx);
                    fma2(acc2[wi * 4 + 3], wb2.y, xx);
                }
            }
        }
    }
    // stage through smem for coalesced stores, apply relu
    __syncthreads();
    float* S = sm;   // 128*2*56 = 14336 floats
    #pragma unroll
    for (int wi = 0; wi < 7; wi++)
        #pragma unroll
        for (int j = 0; j < 4; j++) {
            float2 f = unpk(acc2[wi * 4 + j]);
            S[((ob + 2 * j)     * 2 + hh2) * 56 + wb + wi] = fmaxf(f.x, 0.f);
            S[((ob + 2 * j + 1) * 2 + hh2) * 56 + wb + wi] = fmaxf(f.y, 0.f);
        }
    __syncthreads();
    for (int i = tid; i < 14336; i += 256) {
        int o   = i / 112;
        int rem = i % 112;
        int hh  = rem / 56;
        int w   = rem % 56;
        g_x1r[((size_t)(b * 128 + o) * D_ + d) * HW + (h0 + hh) * 56 + w] = S[i];
    }
}

// ---------------- K6: W_t1 + full Mamba + W_t2 + sigmoid (fused) -----------
// grid 2 (batch), 256 thr, 169KB dyn smem
__global__ void __launch_bounds__(256) k_mamba(
        const float* __restrict__ Wt1,   const float* __restrict__ min_w,
        const float* __restrict__ cw,    const float* __restrict__ cb,
        const float* __restrict__ mx_w,  const float* __restrict__ mdt_w,
        const float* __restrict__ mdt_b, const float* __restrict__ A_log,
        const float* __restrict__ Dp,    const float* __restrict__ mout_w,
        const float* __restrict__ Wt2) {
    extern __shared__ float sm[];
    float* t0s = sm;           // 4096  [c*32 + l]
    float* seq = sm + 4096;    // 4096  [l*128 + h]
    float* xb  = sm + 8192;    // 8192  [l*256 + d]  (later reused as ys)
    float* zb  = sm + 16384;   // 8192
    float* xcv = sm + 24576;   // 8192
    float* dtb = sm + 32768;   // 8192  (later reused as yo [l*128+h])
    float* prb = sm + 40960;   // 1280  [l*40 + j]
    int b = blockIdx.x, tid = threadIdx.x;

    for (int i = tid; i < 4096; i += 256) t0s[i] = g_t0[b * 4096 + i];
    __syncthreads();
    // seq[l][h] = sum_c Wt1[h][c] * t0s[c][l]
    for (int i = tid; i < 4096; i += 256) {
        int l = i >> 7, h = i & 127;
        float a = 0.f;
        for (int c = 0; c < 128; c++) a += Wt1[h * 128 + c] * t0s[c * L_ + l];
        seq[i] = a;
    }
    __syncthreads();
    // xz = seq @ m_in_w.T
    for (int i = tid; i < 16384; i += 256) {
        int l = i >> 9, j = i & 511;
        float a = 0.f;
        const float* wr = &min_w[j * 128];
        for (int h = 0; h < 128; h++) a += wr[h] * seq[l * 128 + h];
        if (j < 256) xb[l * 256 + j] = a;
        else         zb[l * 256 + (j - 256)] = a;
    }
    __syncthreads();
    // causal depthwise conv1d (K=4) + bias + silu
    for (int i = tid; i < 8192; i += 256) {
        int l = i >> 8, dch = i & 255;
        float a = cb[dch];
        #pragma unroll
        for (int k = 0; k < 4; k++) {
            int ll = l - 3 + k;
            if (ll >= 0) a += xb[ll * 256 + dch] * cw[dch * 4 + k];
        }
        xcv[i] = a / (1.f + expf(-a));
    }
    __syncthreads();
    // x_proj: prb[l][0:8]=dt_raw, [8:24]=B, [24:40]=C
    for (int i = tid; i < 1280; i += 256) {
        int l = i / 40, j = i % 40;
        float a = 0.f;
        const float* wr = &mx_w[j * 256];
        for (int dd = 0; dd < 256; dd++) a += wr[dd] * xcv[l * 256 + dd];
        prb[i] = a;
    }
    __syncthreads();
    // dt = softplus(dt_raw @ dt_w.T + dt_b)
    for (int i = tid; i < 8192; i += 256) {
        int l = i >> 8, dch = i & 255;
        float a = mdt_b[dch];
        const float* wr = &mdt_w[dch * 8];
        #pragma unroll
        for (int r = 0; r < 8; r++) a += wr[r] * prb[l * 40 + r];
        dtb[i] = (a > 20.f) ? a : log1pf(expf(a));
    }
    __syncthreads();
    // selective scan: thread tid owns channel dch = tid
    {
        int dch = tid;
        float A[NST], hst[NST];
        #pragma unroll
        for (int n = 0; n < NST; n++) {
            A[n]   = -expf(A_log[dch * NST + n]);
            hst[n] = 0.f;
        }
        float Dv = Dp[dch];
        for (int l = 0; l < L_; l++) {
            float dtv = dtb[l * 256 + dch];
            float xv  = xcv[l * 256 + dch];
            float y = 0.f;
            #pragma unroll
            for (int n = 0; n < NST; n++) {
                float dA = __expf(dtv * A[n]);
                hst[n] = dA * hst[n] + dtv * prb[l * 40 + 8 + n] * xv;
                y += hst[n] * prb[l * 40 + 24 + n];
            }
            y += xv * Dv;
            float zv = zb[l * 256 + dch];
            xb[l * 256 + dch] = y * (zv / (1.f + expf(-zv)));  // ys
        }
    }
    __syncthreads();
    // yo = ys @ m_out_w.T  (reuse dtb)
    for (int i = tid; i < 4096; i += 256) {
        int l = i >> 7, h = i & 127;
        float a = 0.f;
        const float* wr = &mout_w[h * 256];
        for (int dd = 0; dd < 256; dd++) a += wr[dd] * xb[l * 256 + dd];
        dtb[i] = a;
    }
    __syncthreads();
    // gate[o][l] = sigmoid(sum_c Wt2[o][c] * yo[l][c])
    for (int i = tid; i < 4096; i += 256) {
        int o = i >> 5, l = i & 31;
        float a = 0.f;
        const float* wr = &Wt2[o * 128];
        for (int c = 0; c < 128; c++) a += wr[c] * dtb[l * 128 + c];
        g_gate[b * 4096 + o * L_ + l] = 1.f / (1.f + expf(-a));
    }
}

// ---------------- K7: out = W_out @ (x1r * gate) ---------------------------
// grid (784, 2), 256 thr, 96KB smem
__global__ void __launch_bounds__(256) k_out(const float* __restrict__ Wout,
                                             float* __restrict__ out) {
    extern __shared__ float sm[];
    float* Xsh = sm;           // 128*128 = 16384: [c*128 + p]
    float* Wsh = sm + 16384;   // 128*64  =  8192: [c*64 + o]
    int b  = blockIdx.y;
    int p0 = blockIdx.x * 128;
    int tid = threadIdx.x;
    for (int i = tid; i < 8192; i += 256) {
        int o = i >> 7, c = i & 127;
        Wsh[c * 64 + o] = Wout[i];
    }
    for (int i = tid; i < 16384; i += 256) {
        int c = i >> 7, p = i & 127;
        int gp = p0 + p;
        int d  = gp / HW;
        Xsh[i] = g_x1r[(size_t)(b * 128 + c) * P_ + gp] *
                 g_gate[b * 4096 + c * L_ + d];
    }
    __syncthreads();
    int lane = tid & 31;
    int ocb  = (tid >> 5) * 8;
    float acc[4][8];
    #pragma unroll
    for (int j = 0; j < 4; j++)
        #pragma unroll
        for (int oi = 0; oi < 8; oi++) acc[j][oi] = 0.f;
    #pragma unroll 4
    for (int c = 0; c < 128; c++) {
        float xv[4];
        #pragma unroll
        for (int j = 0; j < 4; j++) xv[j] = Xsh[c * 128 + lane + j * 32];
        float4 wa = *(const float4*)&Wsh[c * 64 + ocb];
        float4 wb2 = *(const float4*)&Wsh[c * 64 + ocb + 4];
        float wv[8] = {wa.x, wa.y, wa.z, wa.w, wb2.x, wb2.y, wb2.z, wb2.w};
        #pragma unroll
        for (int j = 0; j < 4; j++)
            #pragma unroll
            for (int oi = 0; oi < 8; oi++)
                acc[j][oi] += wv[oi] * xv[j];
    }
    #pragma unroll
    for (int oi = 0; oi < 8; oi++)
        #pragma unroll
        for (int j = 0; j < 4; j++)
            out[(size_t)(b * 64 + ocb + oi) * P_ + p0 + lane + j * 32] = acc[j][oi];
}

// ---------------- launch ---------------------------------------------------
extern "C" void kernel_launch(void* const* d_in, const int* in_sizes, int n_in,
                              void* d_out, int out_size) {
    const float* inp    = (const float*)d_in[0];
    const float* W_in   = (const float*)d_in[1];
    const float* W_dw   = (const float*)d_in[2];
    const float* W_s    = (const float*)d_in[3];
    const float* W_t1   = (const float*)d_in[4];
    const float* W_t2   = (const float*)d_in[5];
    const float* m_in_w = (const float*)d_in[6];
    const float* m_cw   = (const float*)d_in[7];
    const float* m_cb   = (const float*)d_in[8];
    const float* m_x_w  = (const float*)d_in[9];
    const float* m_dt_w = (const float*)d_in[10];
    const float* m_dt_b = (const float*)d_in[11];
    const float* m_Alog = (const float*)d_in[12];
    const float* m_D    = (const float*)d_in[13];
    const float* m_ow   = (const float*)d_in[14];
    const float* W_out  = (const float*)d_in[15];

    cudaFuncSetAttribute(k_pw,    cudaFuncAttributeMaxDynamicSharedMemorySize, 98304);
    cudaFuncSetAttribute(k_conv,  cudaFuncAttributeMaxDynamicSharedMemorySize, 184320);
    cudaFuncSetAttribute(k_mamba, cudaFuncAttributeMaxDynamicSharedMemorySize, 168960);
    cudaFuncSetAttribute(k_out,   cudaFuncAttributeMaxDynamicSharedMemorySize, 98304);

    k_wt<<<(27 * 128 * 128 + 255) / 256, 256>>>(W_s);
    k_pw<<<dim3(P_ / 128, 2), 256, 98304>>>(inp, W_in);
    k_dw<<<512, 256>>>(W_dw);
    k_conv<<<dim3(28, D_, 2), 256, 184320>>>();
    k_mamba<<<2, 256, 168960>>>(W_t1, m_in_w, m_cw, m_cb, m_x_w, m_dt_w, m_dt_b,
                                m_Alog, m_D, m_ow, W_t2);
    k_out<<<dim3(P_ / 128, 2), 256, 98304>>>(W_out, (float*)d_out);
}

// round 9
// speedup vs baseline: 1.9299x; 1.9299x over previous
#include <cuda_runtime.h>
#include <math.h>
#include <cstdint>

#define D_     32
#define H_     56
#define W_     56
#define HW     3136        // 56*56
#define P_     100352      // 32*56*56
#define NST    16
#define L_     32

// ======================= helpers ===========================================
__device__ __forceinline__ uint32_t smem_u32(const void* p) {
    uint32_t a;
    asm("{ .reg .u64 t; cvta.to.shared.u64 t, %1; cvt.u32.u64 %0, t; }"
        : "=r"(a) : "l"(p));
    return a;
}
__device__ __forceinline__ float to_tf32(float x) {
    uint32_t r;
    asm("cvt.rna.tf32.f32 %0, %1;" : "=r"(r) : "f"(x));
    return __uint_as_float(r);
}
__device__ __forceinline__ void cpasync16(uint32_t smaddr, const void* g) {
    asm volatile("cp.async.ca.shared.global [%0], [%1], 16;"
                 :: "r"(smaddr), "l"(g) : "memory");
}
#define CP_COMMIT() asm volatile("cp.async.commit_group;" ::: "memory")
#define CP_WAIT0()  asm volatile("cp.async.wait_group 0;" ::: "memory")

// m16n8k8 tf32 mma (compute_103-legal; no tcgen05)
__device__ __forceinline__ void mma1688(float* d, const uint32_t* a,
                                        uint32_t b0, uint32_t b1) {
    asm volatile(
        "mma.sync.aligned.m16n8k8.row.col.f32.tf32.tf32.f32 "
        "{%0,%1,%2,%3}, {%4,%5,%6,%7}, {%8,%9}, {%0,%1,%2,%3};"
        : "+f"(d[0]), "+f"(d[1]), "+f"(d[2]), "+f"(d[3])
        : "r"(a[0]), "r"(a[1]), "r"(a[2]), "r"(a[3]), "r"(b0), "r"(b1));
}

// f32x2 helpers (k_pw)
__device__ __forceinline__ void fma2(unsigned long long& d,
                                     unsigned long long a,
                                     unsigned long long b) {
    asm("fma.rn.f32x2 %0, %1, %2, %0;" : "+l"(d) : "l"(a), "l"(b));
}
__device__ __forceinline__ unsigned long long dup2(float x) {
    unsigned long long r;
    asm("mov.b64 %0, {%1, %1};" : "=l"(r) : "f"(x));
    return r;
}
__device__ __forceinline__ float2 unpk(unsigned long long v) {
    float2 f;
    asm("mov.b64 {%0, %1}, %2;" : "=f"(f.x), "=f"(f.y) : "l"(v));
    return f;
}

// ======================= scratch ===========================================
__device__ float g_x   [2 * 256 * P_];
__device__ float g_xc  [2 * 256 * P_];
__device__ float g_x1r [2 * 128 * P_];
__device__ __align__(16) float g_wt[54 * 8704];  // tf32 weights [ch*27+tap][c*136+o]
__device__ float g_t0  [2 * 128 * L_];
__device__ float g_gate[2 * 128 * L_];

// ---------------- K0: weight prep: tf32, per c-half, padded stride 136 -----
__global__ void k_wt(const float* __restrict__ Ws) {
    int i = blockIdx.x * 256 + threadIdx.x;
    if (i >= 54 * 8192) return;
    int cht = i / 8192;            // ch*27 + tap
    int r   = i % 8192;
    int c   = r / 128;             // 0..63 within half
    int o   = r % 128;
    int ch  = cht / 27, tap = cht % 27;
    g_wt[cht * 8704 + c * 136 + o] = to_tf32(Ws[(o * 128 + ch * 64 + c) * 27 + tap]);
}

// ---------------- K1: pointwise conv 64 -> 256 (f32x2) ---------------------
__global__ void __launch_bounds__(256) k_pw(const float* __restrict__ inp,
                                            const float* __restrict__ Win) {
    extern __shared__ float sm[];
    float* Wsh = sm;            // 16384: [c*256 + o]
    float* Ish = sm + 16384;    //  8192: [c*128 + p]
    int b  = blockIdx.y;
    int p0 = blockIdx.x * 128;
    int tid = threadIdx.x;
    for (int i = tid; i < 16384; i += 256) {
        int o = i >> 6, c = i & 63;
        Wsh[c * 256 + o] = Win[i];
    }
    for (int i = tid; i < 8192; i += 256) {
        int c = i >> 7, p = i & 127;
        Ish[i] = inp[(size_t)(b * 64 + c) * P_ + p0 + p];
    }
    __syncthreads();
    int p  = tid & 127;
    int oh = tid >> 7;
    size_t base = (size_t)(b * 256) * P_ + p0 + p;
    for (int oc = 0; oc < 8; oc++) {
        int ob = oh * 128 + oc * 16;
        unsigned long long acc[8];
        #pragma unroll
        for (int j = 0; j < 8; j++) acc[j] = 0ull;
        #pragma unroll 8
        for (int c = 0; c < 64; c++) {
            unsigned long long xx = dup2(Ish[c * 128 + p]);
            const ulonglong2* wp = (const ulonglong2*)&Wsh[c * 256 + ob];
            ulonglong2 w0 = wp[0], w1 = wp[1], w2 = wp[2], w3 = wp[3];
            fma2(acc[0], w0.x, xx); fma2(acc[1], w0.y, xx);
            fma2(acc[2], w1.x, xx); fma2(acc[3], w1.y, xx);
            fma2(acc[4], w2.x, xx); fma2(acc[5], w2.y, xx);
            fma2(acc[6], w3.x, xx); fma2(acc[7], w3.y, xx);
        }
        #pragma unroll
        for (int j = 0; j < 8; j++) {
            float2 f = unpk(acc[j]);
            g_x[base + (size_t)(ob + 2 * j)     * P_] = f.x;
            g_x[base + (size_t)(ob + 2 * j + 1) * P_] = f.y;
        }
    }
}

// ---------------- K2: depthwise 3x3x3 + fused pool -------------------------
__global__ void __launch_bounds__(256) k_dw(const float* __restrict__ Wdw) {
    __shared__ float buf[3][HW];
    __shared__ float red[8];
    int blk = blockIdx.x;
    int b = blk >> 8, c = blk & 255;
    int tid = threadIdx.x;
    int lane = tid & 31, wid = tid >> 5;
    float wreg[27];
    #pragma unroll
    for (int t = 0; t < 27; t++) wreg[t] = Wdw[c * 27 + t];
    const float* src = &g_x [(size_t)(b * 256 + c) * P_];
    float*       dst = &g_xc[(size_t)(b * 256 + c) * P_];
    bool pool = (c >= 128);

    for (int i = tid; i < HW; i += 256) buf[0][i] = src[i];

    for (int d = 0; d < D_; d++) {
        __syncthreads();
        if (d + 1 < D_) {
            float* nb = buf[(d + 1) % 3];
            const float* np = &src[(d + 1) * HW];
            for (int i = tid; i < HW; i += 256) nb[i] = np[i];
        }
        __syncthreads();
        const float* pm1 = (d > 0)      ? buf[(d + 2) % 3] : nullptr;
        const float* p0  =                buf[d % 3];
        const float* pp1 = (d + 1 < D_) ? buf[(d + 1) % 3] : nullptr;
        const float* pl[3] = {pm1, p0, pp1};
        float psum = 0.f;
        for (int i = tid; i < HW; i += 256) {
            int h = i / 56, w = i % 56;
            float acc = 0.f;
            #pragma unroll
            for (int kd = 0; kd < 3; kd++) {
                const float* pn = pl[kd];
                if (!pn) continue;
                #pragma unroll
                for (int kh = 0; kh < 3; kh++) {
                    int hh = h + kh - 1;
                    if ((unsigned)hh >= 56u) continue;
                    const float* row = &pn[hh * 56];
                    #pragma unroll
                    for (int kw = 0; kw < 3; kw++) {
                        int ww = w + kw - 1;
                        if ((unsigned)ww < 56u)
                            acc += wreg[kd * 9 + kh * 3 + kw] * row[ww];
                    }
                }
            }
            dst[d * HW + i] = acc;
            psum += acc;
        }
        if (pool) {
            #pragma unroll
            for (int off = 16; off; off >>= 1)
                psum += __shfl_down_sync(0xffffffffu, psum, off);
            if (lane == 0) red[wid] = psum;
            __syncthreads();
            if (tid == 0) {
                float s = 0.f;
                #pragma unroll
                for (int j = 0; j < 8; j++) s += red[j];
                g_t0[(b * 128 + (c - 128)) * L_ + d] = s * (1.f / 3136.f);
            }
        }
    }
}

// ---------------- K3: dense 3x3x3 conv 128->128 via mma.sync tf32 ----------
// Block = (b, d, 4 h-rows). M=128 o, N=224 px, K=128c*27taps.
// 8 warps: ogrp = wid&1 (64 o), hh = wid>>1 (one h-row, 56 px = 7 n8 tiles).
#define WP_    72                 // padded Ish row (bank-conflict-free B frags)
#define CHALF  64
#define ISH_F  (6 * CHALF * WP_)  // 27648 floats
#define WSH_F  8704               // 64*136 (bank-conflict-free A frags)
#define CONV_SM ((ISH_F + 2 * WSH_F) * 4)   // 180224 B

__global__ void __launch_bounds__(256, 1) k_conv() {
    extern __shared__ float sm[];
    float* Ish  = sm;
    float* Wsh0 = sm + ISH_F;
    float* Wsh1 = sm + ISH_F + WSH_F;
    int b  = blockIdx.z;
    int d  = blockIdx.y;
    int h0 = blockIdx.x * 4;
    int tid = threadIdx.x;
    int wid = tid >> 5, lane = tid & 31;
    int lr = lane >> 2, lc = lane & 3;
    int ogrp = wid & 1, hh = wid >> 1;

    int dds[3]; int nkd = 0;
    #pragma unroll
    for (int kd = 0; kd < 3; kd++) {
        int dd = d + kd - 1;
        if (dd >= 0 && dd < D_) dds[nkd++] = dd;
    }
    int tapsPer = nkd * 9;
    int ntap = 2 * tapsPer;

    float acc[4][7][4];
    #pragma unroll
    for (int m = 0; m < 4; m++)
        #pragma unroll
        for (int j = 0; j < 7; j++)
            #pragma unroll
            for (int r = 0; r < 4; r++) acc[m][j][r] = 0.f;

    // prefetch tap 0 weights
    {
        int kdi = 0, t9 = 0, ch = 0;
        const float* g = &g_wt[(ch * 27 + (dds[kdi] - (d - 1)) * 9 + t9) * 8704];
        uint32_t sa = smem_u32(Wsh0);
        for (int i = tid; i < WSH_F / 4; i += 256)
            cpasync16(sa + i * 16, (const char*)g + i * 16);
        CP_COMMIT();
    }

    for (int T = 0; T < ntap; T++) {
        CP_WAIT0();
        __syncthreads();
        if (T + 1 < ntap) {
            int Tn = T + 1;
            int chn = Tn / tapsPer, rn = Tn % tapsPer;
            int kdin = rn / 9, t9n = rn % 9;
            const float* g = &g_wt[(chn * 27 + (dds[kdin] - (d - 1)) * 9 + t9n) * 8704];
            uint32_t sa = smem_u32(((Tn & 1) ? Wsh1 : Wsh0));
            for (int i = tid; i < WSH_F / 4; i += 256)
                cpasync16(sa + i * 16, (const char*)g + i * 16);
            CP_COMMIT();
        }
        int ch = T / tapsPer, r2 = T % tapsPer;
        int kdi = r2 / 9, t9 = r2 % 9, kh = t9 / 3, kw = t9 % 3;
        if (t9 == 0) {   // new (ch, kd) plane -> refill Ish
            const float* src = &g_xc[((size_t)(b * 256 + ch * 64) * D_ + dds[kdi]) * HW];
            for (int i = tid; i < 6 * CHALF * 58; i += 256) {
                int r   = i / (CHALF * 58);
                int rem = i % (CHALF * 58);
                int c   = rem / 58;
                int wp  = rem % 58;
                int ih  = h0 + r - 1;
                int w   = wp - 1;
                float v = 0.f;
                if ((unsigned)ih < 56u && (unsigned)w < 56u)
                    v = to_tf32(src[(size_t)c * (D_ * HW) + ih * 56 + w]);
                Ish[(r * CHALF + c) * WP_ + wp] = v;
            }
            __syncthreads();
        }
        const float* Wb = (T & 1) ? Wsh1 : Wsh0;
        const float* AB = &Wb[lc * 136 + ogrp * 64 + lr];
        const float* BB = &Ish[((hh + kh) * CHALF + lc) * WP_ + lr + kw];
        #pragma unroll
        for (int ks = 0; ks < 8; ks++) {
            uint32_t a[4][4];
            const float* Ab = AB + ks * 8 * 136;
            #pragma unroll
            for (int mt = 0; mt < 4; mt++) {
                const float* p = Ab + mt * 16;
                a[mt][0] = __float_as_uint(p[0]);
                a[mt][1] = __float_as_uint(p[8]);
                a[mt][2] = __float_as_uint(p[544]);
                a[mt][3] = __float_as_uint(p[552]);
            }
            const float* Bb = BB + ks * 8 * WP_;
            #pragma unroll
            for (int j = 0; j < 7; j++) {
                uint32_t b0 = __float_as_uint(Bb[j * 8]);
                uint32_t b1 = __float_as_uint(Bb[j * 8 + 4 * WP_]);
                #pragma unroll
                for (int mt = 0; mt < 4; mt++)
                    mma1688(acc[mt][j], a[mt], b0, b1);
            }
        }
    }
    // ---- epilogue: relu, stage (coalesce), store --------------------------
    __syncthreads();
    float* stage = sm;     // [o][228]
    #pragma unroll
    for (int mt = 0; mt < 4; mt++) {
        int o = ogrp * 64 + mt * 16 + lr;
        #pragma unroll
        for (int j = 0; j < 7; j++) {
            int n = hh * 56 + j * 8 + lc * 2;
            stage[o * 228 + n]           = fmaxf(acc[mt][j][0], 0.f);
            stage[o * 228 + n + 1]       = fmaxf(acc[mt][j][1], 0.f);
            stage[(o + 8) * 228 + n]     = fmaxf(acc[mt][j][2], 0.f);
            stage[(o + 8) * 228 + n + 1] = fmaxf(acc[mt][j][3], 0.f);
        }
    }
    __syncthreads();
    for (int i = tid; i < 128 * 224; i += 256) {
        int o   = i / 224;
        int rem = i % 224;
        int h2  = rem / 56;
        int w   = rem % 56;
        g_x1r[((size_t)(b * 128 + o) * D_ + d) * HW + (h0 + h2) * 56 + w] =
            stage[o * 228 + h2 * 56 + w];
    }
}

// ---------------- K6: W_t1 + full Mamba + W_t2 + sigmoid (fused) -----------
__global__ void __launch_bounds__(256) k_mamba(
        const float* __restrict__ Wt1,   const float* __restrict__ min_w,
        const float* __restrict__ cw,    const float* __restrict__ cb,
        const float* __restrict__ mx_w,  const float* __restrict__ mdt_w,
        const float* __restrict__ mdt_b, const float* __restrict__ A_log,
        const float* __restrict__ Dp,    const float* __restrict__ mout_w,
        const float* __restrict__ Wt2) {
    extern __shared__ float sm[];
    float* t0s = sm;           // 4096
    float* seq = sm + 4096;    // 4096
    float* xb  = sm + 8192;    // 8192
    float* zb  = sm + 16384;   // 8192
    float* xcv = sm + 24576;   // 8192
    float* dtb = sm + 32768;   // 8192
    float* prb = sm + 40960;   // 1280
    int b = blockIdx.x, tid = threadIdx.x;

    for (int i = tid; i < 4096; i += 256) t0s[i] = g_t0[b * 4096 + i];
    __syncthreads();
    for (int i = tid; i < 4096; i += 256) {
        int l = i >> 7, h = i & 127;
        float a = 0.f;
        for (int c = 0; c < 128; c++) a += Wt1[h * 128 + c] * t0s[c * L_ + l];
        seq[i] = a;
    }
    __syncthreads();
    for (int i = tid; i < 16384; i += 256) {
        int l = i >> 9, j = i & 511;
        float a = 0.f;
        const float* wr = &min_w[j * 128];
        for (int h = 0; h < 128; h++) a += wr[h] * seq[l * 128 + h];
        if (j < 256) xb[l * 256 + j] = a;
        else         zb[l * 256 + (j - 256)] = a;
    }
    __syncthreads();
    for (int i = tid; i < 8192; i += 256) {
        int l = i >> 8, dch = i & 255;
        float a = cb[dch];
        #pragma unroll
        for (int k = 0; k < 4; k++) {
            int ll = l - 3 + k;
            if (ll >= 0) a += xb[ll * 256 + dch] * cw[dch * 4 + k];
        }
        xcv[i] = a / (1.f + expf(-a));
    }
    __syncthreads();
    for (int i = tid; i < 1280; i += 256) {
        int l = i / 40, j = i % 40;
        float a = 0.f;
        const float* wr = &mx_w[j * 256];
        for (int dd = 0; dd < 256; dd++) a += wr[dd] * xcv[l * 256 + dd];
        prb[i] = a;
    }
    __syncthreads();
    for (int i = tid; i < 8192; i += 256) {
        int l = i >> 8, dch = i & 255;
        float a = mdt_b[dch];
        const float* wr = &mdt_w[dch * 8];
        #pragma unroll
        for (int r = 0; r < 8; r++) a += wr[r] * prb[l * 40 + r];
        dtb[i] = (a > 20.f) ? a : log1pf(expf(a));
    }
    __syncthreads();
    {
        int dch = tid;
        float A[NST], hst[NST];
        #pragma unroll
        for (int n = 0; n < NST; n++) {
            A[n]   = -expf(A_log[dch * NST + n]);
            hst[n] = 0.f;
        }
        float Dv = Dp[dch];
        for (int l = 0; l < L_; l++) {
            float dtv = dtb[l * 256 + dch];
            float xv  = xcv[l * 256 + dch];
            float y = 0.f;
            #pragma unroll
            for (int n = 0; n < NST; n++) {
                float dA = __expf(dtv * A[n]);
                hst[n] = dA * hst[n] + dtv * prb[l * 40 + 8 + n] * xv;
                y += hst[n] * prb[l * 40 + 24 + n];
            }
            y += xv * Dv;
            float zv = zb[l * 256 + dch];
            xb[l * 256 + dch] = y * (zv / (1.f + expf(-zv)));
        }
    }
    __syncthreads();
    for (int i = tid; i < 4096; i += 256) {
        int l = i >> 7, h = i & 127;
        float a = 0.f;
        const float* wr = &mout_w[h * 256];
        for (int dd = 0; dd < 256; dd++) a += wr[dd] * xb[l * 256 + dd];
        dtb[i] = a;
    }
    __syncthreads();
    for (int i = tid; i < 4096; i += 256) {
        int o = i >> 5, l = i & 31;
        float a = 0.f;
        const float* wr = &Wt2[o * 128];
        for (int c = 0; c < 128; c++) a += wr[c] * dtb[l * 128 + c];
        g_gate[b * 4096 + o * L_ + l] = 1.f / (1.f + expf(-a));
    }
}

// ---------------- K7: out = W_out @ (x1r * gate) ---------------------------
__global__ void __launch_bounds__(256) k_out(const float* __restrict__ Wout,
                                             float* __restrict__ out) {
    extern __shared__ float sm[];
    float* Xsh = sm;           // 16384: [c*128 + p]
    float* Wsh = sm + 16384;   //  8192: [c*64 + o]
    int b  = blockIdx.y;
    int p0 = blockIdx.x * 128;
    int tid = threadIdx.x;
    for (int i = tid; i < 8192; i += 256) {
        int o = i >> 7, c = i & 127;
        Wsh[c * 64 + o] = Wout[i];
    }
    for (int i = tid; i < 16384; i += 256) {
        int c = i >> 7, p = i & 127;
        int gp = p0 + p;
        int d  = gp / HW;
        Xsh[i] = g_x1r[(size_t)(b * 128 + c) * P_ + gp] *
                 g_gate[b * 4096 + c * L_ + d];
    }
    __syncthreads();
    int lane = tid & 31;
    int ocb  = (tid >> 5) * 8;
    float acc[4][8];
    #pragma unroll
    for (int j = 0; j < 4; j++)
        #pragma unroll
        for (int oi = 0; oi < 8; oi++) acc[j][oi] = 0.f;
    #pragma unroll 4
    for (int c = 0; c < 128; c++) {
        float xv[4];
        #pragma unroll
        for (int j = 0; j < 4; j++) xv[j] = Xsh[c * 128 + lane + j * 32];
        float4 wa = *(const float4*)&Wsh[c * 64 + ocb];
        float4 wb2 = *(const float4*)&Wsh[c * 64 + ocb + 4];
        float wv[8] = {wa.x, wa.y, wa.z, wa.w, wb2.x, wb2.y, wb2.z, wb2.w};
        #pragma unroll
        for (int j = 0; j < 4; j++)
            #pragma unroll
            for (int oi = 0; oi < 8; oi++)
                acc[j][oi] += wv[oi] * xv[j];
    }
    #pragma unroll
    for (int oi = 0; oi < 8; oi++)
        #pragma unroll
        for (int j = 0; j < 4; j++)
            out[(size_t)(b * 64 + ocb + oi) * P_ + p0 + lane + j * 32] = acc[j][oi];
}

// ---------------- launch ---------------------------------------------------
extern "C" void kernel_launch(void* const* d_in, const int* in_sizes, int n_in,
                              void* d_out, int out_size) {
    const float* inp    = (const float*)d_in[0];
    const float* W_in   = (const float*)d_in[1];
    const float* W_dw   = (const float*)d_in[2];
    const float* W_s    = (const float*)d_in[3];
    const float* W_t1   = (const float*)d_in[4];
    const float* W_t2   = (const float*)d_in[5];
    const float* m_in_w = (const float*)d_in[6];
    const float* m_cw   = (const float*)d_in[7];
    const float* m_cb   = (const float*)d_in[8];
    const float* m_x_w  = (const float*)d_in[9];
    const float* m_dt_w = (const float*)d_in[10];
    const float* m_dt_b = (const float*)d_in[11];
    const float* m_Alog = (const float*)d_in[12];
    const float* m_D    = (const float*)d_in[13];
    const float* m_ow   = (const float*)d_in[14];
    const float* W_out  = (const float*)d_in[15];

    cudaFuncSetAttribute(k_pw,    cudaFuncAttributeMaxDynamicSharedMemorySize, 98304);
    cudaFuncSetAttribute(k_conv,  cudaFuncAttributeMaxDynamicSharedMemorySize, CONV_SM);
    cudaFuncSetAttribute(k_mamba, cudaFuncAttributeMaxDynamicSharedMemorySize, 168960);
    cudaFuncSetAttribute(k_out,   cudaFuncAttributeMaxDynamicSharedMemorySize, 98304);

    k_wt<<<(54 * 8192 + 255) / 256, 256>>>(W_s);
    k_pw<<<dim3(P_ / 128, 2), 256, 98304>>>(inp, W_in);
    k_dw<<<512, 256>>>(W_dw);
    k_conv<<<dim3(14, D_, 2), 256, CONV_SM>>>();
    k_mamba<<<2, 256, 168960>>>(W_t1, m_in_w, m_cw, m_cb, m_x_w, m_dt_w, m_dt_b,
                                m_Alog, m_D, m_ow, W_t2);
    k_out<<<dim3(P_ / 128, 2), 256, 98304>>>(W_out, (float*)d_out);
}

// round 14
// speedup vs baseline: 2.0115x; 1.0423x over previous
#include <cuda_runtime.h>
#include <math.h>
#include <cstdint>

#define D_     32
#define H_     56
#define W_     56
#define HW     3136        // 56*56
#define P_     100352      // 32*56*56
#define NST    16
#define L_     32

// ======================= helpers ===========================================
__device__ __forceinline__ uint32_t smem_u32(const void* p) {
    uint32_t a;
    asm("{ .reg .u64 t; cvta.to.shared.u64 t, %1; cvt.u32.u64 %0, t; }"
        : "=r"(a) : "l"(p));
    return a;
}
__device__ __forceinline__ float to_tf32(float x) {
    uint32_t r;
    asm("cvt.rna.tf32.f32 %0, %1;" : "=r"(r) : "f"(x));
    return __uint_as_float(r);
}
__device__ __forceinline__ void cpasync16(uint32_t smaddr, const void* g) {
    asm volatile("cp.async.ca.shared.global [%0], [%1], 16;"
                 :: "r"(smaddr), "l"(g) : "memory");
}
#define CP_COMMIT() asm volatile("cp.async.commit_group;" ::: "memory")
#define CP_WAIT0()  asm volatile("cp.async.wait_group 0;" ::: "memory")

// m16n8k8 tf32 mma (compute_103-legal; no tcgen05)
__device__ __forceinline__ void mma1688(float* d, const uint32_t* a,
                                        uint32_t b0, uint32_t b1) {
    asm volatile(
        "mma.sync.aligned.m16n8k8.row.col.f32.tf32.tf32.f32 "
        "{%0,%1,%2,%3}, {%4,%5,%6,%7}, {%8,%9}, {%0,%1,%2,%3};"
        : "+f"(d[0]), "+f"(d[1]), "+f"(d[2]), "+f"(d[3])
        : "r"(a[0]), "r"(a[1]), "r"(a[2]), "r"(a[3]), "r"(b0), "r"(b1));
}

// f32x2 helpers (k_pw)
__device__ __forceinline__ void fma2(unsigned long long& d,
                                     unsigned long long a,
                                     unsigned long long b) {
    asm("fma.rn.f32x2 %0, %1, %2, %0;" : "+l"(d) : "l"(a), "l"(b));
}
__device__ __forceinline__ unsigned long long dup2(float x) {
    unsigned long long r;
    asm("mov.b64 %0, {%1, %1};" : "=l"(r) : "f"(x));
    return r;
}
__device__ __forceinline__ float2 unpk(unsigned long long v) {
    float2 f;
    asm("mov.b64 {%0, %1}, %2;" : "=f"(f.x), "=f"(f.y) : "l"(v));
    return f;
}

// ======================= scratch ===========================================
__device__ float g_x   [2 * 256 * P_];
__device__ float g_xc  [2 * 256 * P_];
__device__ float g_x1r [2 * 128 * P_];
__device__ __align__(16) float g_wt[54 * 8704];  // tf32 weights [ch*27+tap][c*136+o]
__device__ float g_t0  [2 * 128 * L_];
__device__ float g_gate[2 * 128 * L_];

// ---------------- K0: weight prep: tf32, per c-half, padded stride 136 -----
__global__ void k_wt(const float* __restrict__ Ws) {
    int i = blockIdx.x * 256 + threadIdx.x;
    if (i >= 54 * 8192) return;
    int cht = i / 8192;            // ch*27 + tap
    int r   = i % 8192;
    int c   = r / 128;             // 0..63 within half
    int o   = r % 128;
    int ch  = cht / 27, tap = cht % 27;
    g_wt[cht * 8704 + c * 136 + o] = to_tf32(Ws[(o * 128 + ch * 64 + c) * 27 + tap]);
}

// ---------------- K1: pointwise conv 64 -> 256 (f32x2) ---------------------
__global__ void __launch_bounds__(256) k_pw(const float* __restrict__ inp,
                                            const float* __restrict__ Win) {
    extern __shared__ float sm[];
    float* Wsh = sm;            // 16384: [c*256 + o]
    float* Ish = sm + 16384;    //  8192: [c*128 + p]
    int b  = blockIdx.y;
    int p0 = blockIdx.x * 128;
    int tid = threadIdx.x;
    for (int i = tid; i < 16384; i += 256) {
        int o = i >> 6, c = i & 63;
        Wsh[c * 256 + o] = Win[i];
    }
    for (int i = tid; i < 8192; i += 256) {
        int c = i >> 7, p = i & 127;
        Ish[i] = inp[(size_t)(b * 64 + c) * P_ + p0 + p];
    }
    __syncthreads();
    int p  = tid & 127;
    int oh = tid >> 7;
    size_t base = (size_t)(b * 256) * P_ + p0 + p;
    for (int oc = 0; oc < 8; oc++) {
        int ob = oh * 128 + oc * 16;
        unsigned long long acc[8];
        #pragma unroll
        for (int j = 0; j < 8; j++) acc[j] = 0ull;
        #pragma unroll 8
        for (int c = 0; c < 64; c++) {
            unsigned long long xx = dup2(Ish[c * 128 + p]);
            const ulonglong2* wp = (const ulonglong2*)&Wsh[c * 256 + ob];
            ulonglong2 w0 = wp[0], w1 = wp[1], w2 = wp[2], w3 = wp[3];
            fma2(acc[0], w0.x, xx); fma2(acc[1], w0.y, xx);
            fma2(acc[2], w1.x, xx); fma2(acc[3], w1.y, xx);
            fma2(acc[4], w2.x, xx); fma2(acc[5], w2.y, xx);
            fma2(acc[6], w3.x, xx); fma2(acc[7], w3.y, xx);
        }
        #pragma unroll
        for (int j = 0; j < 8; j++) {
            float2 f = unpk(acc[j]);
            g_x[base + (size_t)(ob + 2 * j)     * P_] = f.x;
            g_x[base + (size_t)(ob + 2 * j + 1) * P_] = f.y;
        }
    }
}

// ---------------- K2: depthwise 3x3x3 + fused pool -------------------------
__global__ void __launch_bounds__(256) k_dw(const float* __restrict__ Wdw) {
    __shared__ float buf[3][HW];
    __shared__ float red[8];
    int blk = blockIdx.x;
    int b = blk >> 8, c = blk & 255;
    int tid = threadIdx.x;
    int lane = tid & 31, wid = tid >> 5;
    float wreg[27];
    #pragma unroll
    for (int t = 0; t < 27; t++) wreg[t] = Wdw[c * 27 + t];
    const float* src = &g_x [(size_t)(b * 256 + c) * P_];
    float*       dst = &g_xc[(size_t)(b * 256 + c) * P_];
    bool pool = (c >= 128);

    for (int i = tid; i < HW; i += 256) buf[0][i] = src[i];

    for (int d = 0; d < D_; d++) {
        __syncthreads();
        if (d + 1 < D_) {
            float* nb = buf[(d + 1) % 3];
            const float* np = &src[(d + 1) * HW];
            for (int i = tid; i < HW; i += 256) nb[i] = np[i];
        }
        __syncthreads();
        const float* pm1 = (d > 0)      ? buf[(d + 2) % 3] : nullptr;
        const float* p0  =                buf[d % 3];
        const float* pp1 = (d + 1 < D_) ? buf[(d + 1) % 3] : nullptr;
        const float* pl[3] = {pm1, p0, pp1};
        float psum = 0.f;
        for (int i = tid; i < HW; i += 256) {
            int h = i / 56, w = i % 56;
            float acc = 0.f;
            #pragma unroll
            for (int kd = 0; kd < 3; kd++) {
                const float* pn = pl[kd];
                if (!pn) continue;
                #pragma unroll
                for (int kh = 0; kh < 3; kh++) {
                    int hh = h + kh - 1;
                    if ((unsigned)hh >= 56u) continue;
                    const float* row = &pn[hh * 56];
                    #pragma unroll
                    for (int kw = 0; kw < 3; kw++) {
                        int ww = w + kw - 1;
                        if ((unsigned)ww < 56u)
                            acc += wreg[kd * 9 + kh * 3 + kw] * row[ww];
                    }
                }
            }
            dst[d * HW + i] = acc;
            psum += acc;
        }
        if (pool) {
            #pragma unroll
            for (int off = 16; off; off >>= 1)
                psum += __shfl_down_sync(0xffffffffu, psum, off);
            if (lane == 0) red[wid] = psum;
            __syncthreads();
            if (tid == 0) {
                float s = 0.f;
                #pragma unroll
                for (int j = 0; j < 8; j++) s += red[j];
                g_t0[(b * 128 + (c - 128)) * L_ + d] = s * (1.f / 3136.f);
            }
        }
    }
}

// ---------------- K3: dense 3x3x3 conv 128->128 via mma.sync tf32 ----------
// Block = (b, d, 4 h-rows), 512 thr / 16 warps. M=128 o, N=224 px, K=128c*27.
// Warp: og4 = wid&3 -> 32 o (2 m16 tiles), hh = wid>>2 -> one h-row (7 n8).
#define WP_    72                 // padded Ish row (bank-conflict-free B frags)
#define CHALF  64
#define ISH_F  (6 * CHALF * WP_)  // 27648 floats
#define WSH_F  8704               // 64*136 (bank-conflict-free A frags)
#define CONV_SM ((ISH_F + 2 * WSH_F) * 4)   // 180224 B
#define CTH    512

__global__ void __launch_bounds__(CTH, 1) k_conv() {
    extern __shared__ float sm[];
    float* Ish  = sm;
    float* Wsh0 = sm + ISH_F;
    float* Wsh1 = sm + ISH_F + WSH_F;
    int b  = blockIdx.z;
    int d  = blockIdx.y;
    int h0 = blockIdx.x * 4;
    int tid = threadIdx.x;
    int wid = tid >> 5, lane = tid & 31;
    int lr = lane >> 2, lc = lane & 3;
    int og4 = wid & 3, hh = wid >> 2;

    int dds[3]; int nkd = 0;
    #pragma unroll
    for (int kd = 0; kd < 3; kd++) {
        int dd = d + kd - 1;
        if (dd >= 0 && dd < D_) dds[nkd++] = dd;
    }
    int tapsPer = nkd * 9;
    int ntap = 2 * tapsPer;

    float acc[2][7][4];
    #pragma unroll
    for (int m = 0; m < 2; m++)
        #pragma unroll
        for (int j = 0; j < 7; j++)
            #pragma unroll
            for (int r = 0; r < 4; r++) acc[m][j][r] = 0.f;

    // prefetch tap 0 weights
    {
        const float* g = &g_wt[((dds[0] - (d - 1)) * 9) * 8704];
        uint32_t sa = smem_u32(Wsh0);
        for (int i = tid; i < WSH_F / 4; i += CTH)
            cpasync16(sa + i * 16, (const char*)g + i * 16);
        CP_COMMIT();
    }

    for (int T = 0; T < ntap; T++) {
        CP_WAIT0();
        __syncthreads();
        if (T + 1 < ntap) {
            int Tn = T + 1;
            int chn = Tn / tapsPer, rn = Tn % tapsPer;
            int kdin = rn / 9, t9n = rn % 9;
            const float* g = &g_wt[(chn * 27 + (dds[kdin] - (d - 1)) * 9 + t9n) * 8704];
            uint32_t sa = smem_u32(((Tn & 1) ? Wsh1 : Wsh0));
            for (int i = tid; i < WSH_F / 4; i += CTH)
                cpasync16(sa + i * 16, (const char*)g + i * 16);
            CP_COMMIT();
        }
        int ch = T / tapsPer, r2 = T % tapsPer;
        int kdi = r2 / 9, t9 = r2 % 9, kh = t9 / 3, kw = t9 % 3;
        if (t9 == 0) {   // new (ch, kd) plane -> refill Ish
            const float* src = &g_xc[((size_t)(b * 256 + ch * 64) * D_ + dds[kdi]) * HW];
            for (int i = tid; i < 6 * CHALF * 58; i += CTH) {
                int r   = i / (CHALF * 58);
                int rem = i % (CHALF * 58);
                int c   = rem / 58;
                int wp  = rem % 58;
                int ih  = h0 + r - 1;
                int w   = wp - 1;
                float v = 0.f;
                if ((unsigned)ih < 56u && (unsigned)w < 56u)
                    v = to_tf32(src[(size_t)c * (D_ * HW) + ih * 56 + w]);
                Ish[(r * CHALF + c) * WP_ + wp] = v;
            }
            __syncthreads();
        }
        const float* Wb = (T & 1) ? Wsh1 : Wsh0;
        const float* AB = &Wb[lc * 136 + og4 * 32 + lr];
        const float* BB = &Ish[((hh + kh) * CHALF + lc) * WP_ + lr + kw];
        #pragma unroll
        for (int ks = 0; ks < 8; ks++) {
            uint32_t a[2][4];
            const float* Ab = AB + ks * 8 * 136;
            #pragma unroll
            for (int mt = 0; mt < 2; mt++) {
                const float* p = Ab + mt * 16;
                a[mt][0] = __float_as_uint(p[0]);
                a[mt][1] = __float_as_uint(p[8]);
                a[mt][2] = __float_as_uint(p[544]);
                a[mt][3] = __float_as_uint(p[552]);
            }
            const float* Bb = BB + ks * 8 * WP_;
            #pragma unroll
            for (int j = 0; j < 7; j++) {
                uint32_t b0 = __float_as_uint(Bb[j * 8]);
                uint32_t b1 = __float_as_uint(Bb[j * 8 + 4 * WP_]);
                #pragma unroll
                for (int mt = 0; mt < 2; mt++)
                    mma1688(acc[mt][j], a[mt], b0, b1);
            }
        }
    }
    // ---- epilogue: relu, stage (coalesce), store --------------------------
    __syncthreads();
    float* stage = sm;     // [o][228] = 29184 floats (116.7KB < 176KB)
    #pragma unroll
    for (int mt = 0; mt < 2; mt++) {
        int o = og4 * 32 + mt * 16 + lr;
        #pragma unroll
        for (int j = 0; j < 7; j++) {
            int n = hh * 56 + j * 8 + lc * 2;
            stage[o * 228 + n]           = fmaxf(acc[mt][j][0], 0.f);
            stage[o * 228 + n + 1]       = fmaxf(acc[mt][j][1], 0.f);
            stage[(o + 8) * 228 + n]     = fmaxf(acc[mt][j][2], 0.f);
            stage[(o + 8) * 228 + n + 1] = fmaxf(acc[mt][j][3], 0.f);
        }
    }
    __syncthreads();
    for (int i = tid; i < 128 * 224; i += CTH) {
        int o   = i / 224;
        int rem = i % 224;
        int h2  = rem / 56;
        int w   = rem % 56;
        g_x1r[((size_t)(b * 128 + o) * D_ + d) * HW + (h0 + h2) * 56 + w] =
            stage[o * 228 + h2 * 56 + w];
    }
}

// ---------------- K6: W_t1 + full Mamba + W_t2 + sigmoid (fused) -----------
__global__ void __launch_bounds__(256) k_mamba(
        const float* __restrict__ Wt1,   const float* __restrict__ min_w,
        const float* __restrict__ cw,    const float* __restrict__ cb,
        const float* __restrict__ mx_w,  const float* __restrict__ mdt_w,
        const float* __restrict__ mdt_b, const float* __restrict__ A_log,
        const float* __restrict__ Dp,    const float* __restrict__ mout_w,
        const float* __restrict__ Wt2) {
    extern __shared__ float sm[];
    float* t0s = sm;           // 4096
    float* seq = sm + 4096;    // 4096
    float* xb  = sm + 8192;    // 8192
    float* zb  = sm + 16384;   // 8192
    float* xcv = sm + 24576;   // 8192
    float* dtb = sm + 32768;   // 8192
    float* prb = sm + 40960;   // 1280
    int b = blockIdx.x, tid = threadIdx.x;

    for (int i = tid; i < 4096; i += 256) t0s[i] = g_t0[b * 4096 + i];
    __syncthreads();
    for (int i = tid; i < 4096; i += 256) {
        int l = i >> 7, h = i & 127;
        float a = 0.f;
        for (int c = 0; c < 128; c++) a += Wt1[h * 128 + c] * t0s[c * L_ + l];
        seq[i] = a;
    }
    __syncthreads();
    for (int i = tid; i < 16384; i += 256) {
        int l = i >> 9, j = i & 511;
        float a = 0.f;
        const float* wr = &min_w[j * 128];
        for (int h = 0; h < 128; h++) a += wr[h] * seq[l * 128 + h];
        if (j < 256) xb[l * 256 + j] = a;
        else         zb[l * 256 + (j - 256)] = a;
    }
    __syncthreads();
    for (int i = tid; i < 8192; i += 256) {
        int l = i >> 8, dch = i & 255;
        float a = cb[dch];
        #pragma unroll
        for (int k = 0; k < 4; k++) {
            int ll = l - 3 + k;
            if (ll >= 0) a += xb[ll * 256 + dch] * cw[dch * 4 + k];
        }
        xcv[i] = a / (1.f + expf(-a));
    }
    __syncthreads();
    for (int i = tid; i < 1280; i += 256) {
        int l = i / 40, j = i % 40;
        float a = 0.f;
        const float* wr = &mx_w[j * 256];
        for (int dd = 0; dd < 256; dd++) a += wr[dd] * xcv[l * 256 + dd];
        prb[i] = a;
    }
    __syncthreads();
    for (int i = tid; i < 8192; i += 256) {
        int l = i >> 8, dch = i & 255;
        float a = mdt_b[dch];
        const float* wr = &mdt_w[dch * 8];
        #pragma unroll
        for (int r = 0; r < 8; r++) a += wr[r] * prb[l * 40 + r];
        dtb[i] = (a > 20.f) ? a : log1pf(expf(a));
    }
    __syncthreads();
    {
        int dch = tid;
        float A[NST], hst[NST];
        #pragma unroll
        for (int n = 0; n < NST; n++) {
            A[n]   = -expf(A_log[dch * NST + n]);
            hst[n] = 0.f;
        }
        float Dv = Dp[dch];
        for (int l = 0; l < L_; l++) {
            float dtv = dtb[l * 256 + dch];
            float xv  = xcv[l * 256 + dch];
            float y = 0.f;
            #pragma unroll
            for (int n = 0; n < NST; n++) {
                float dA = __expf(dtv * A[n]);
                hst[n] = dA * hst[n] + dtv * prb[l * 40 + 8 + n] * xv;
                y += hst[n] * prb[l * 40 + 24 + n];
            }
            y += xv * Dv;
            float zv = zb[l * 256 + dch];
            xb[l * 256 + dch] = y * (zv / (1.f + expf(-zv)));
        }
    }
    __syncthreads();
    for (int i = tid; i < 4096; i += 256) {
        int l = i >> 7, h = i & 127;
        float a = 0.f;
        const float* wr = &mout_w[h * 256];
        for (int dd = 0; dd < 256; dd++) a += wr[dd] * xb[l * 256 + dd];
        dtb[i] = a;
    }
    __syncthreads();
    for (int i = tid; i < 4096; i += 256) {
        int o = i >> 5, l = i & 31;
        float a = 0.f;
        const float* wr = &Wt2[o * 128];
        for (int c = 0; c < 128; c++) a += wr[c] * dtb[l * 128 + c];
        g_gate[b * 4096 + o * L_ + l] = 1.f / (1.f + expf(-a));
    }
}

// ---------------- K7: out = W_out @ (x1r * gate) ---------------------------
__global__ void __launch_bounds__(256) k_out(const float* __restrict__ Wout,
                                             float* __restrict__ out) {
    extern __shared__ float sm[];
    float* Xsh = sm;           // 16384: [c*128 + p]
    float* Wsh = sm + 16384;   //  8192: [c*64 + o]
    int b  = blockIdx.y;
    int p0 = blockIdx.x * 128;
    int tid = threadIdx.x;
    for (int i = tid; i < 8192; i += 256) {
        int o = i >> 7, c = i & 127;
        Wsh[c * 64 + o] = Wout[i];
    }
    for (int i = tid; i < 16384; i += 256) {
        int c = i >> 7, p = i & 127;
        int gp = p0 + p;
        int d  = gp / HW;
        Xsh[i] = g_x1r[(size_t)(b * 128 + c) * P_ + gp] *
                 g_gate[b * 4096 + c * L_ + d];
    }
    __syncthreads();
    int lane = tid & 31;
    int ocb  = (tid >> 5) * 8;
    float acc[4][8];
    #pragma unroll
    for (int j = 0; j < 4; j++)
        #pragma unroll
        for (int oi = 0; oi < 8; oi++) acc[j][oi] = 0.f;
    #pragma unroll 4
    for (int c = 0; c < 128; c++) {
        float xv[4];
        #pragma unroll
        for (int j = 0; j < 4; j++) xv[j] = Xsh[c * 128 + lane + j * 32];
        float4 wa = *(const float4*)&Wsh[c * 64 + ocb];
        float4 wb2 = *(const float4*)&Wsh[c * 64 + ocb + 4];
        float wv[8] = {wa.x, wa.y, wa.z, wa.w, wb2.x, wb2.y, wb2.z, wb2.w};
        #pragma unroll
        for (int j = 0; j < 4; j++)
            #pragma unroll
            for (int oi = 0; oi < 8; oi++)
                acc[j][oi] += wv[oi] * xv[j];
    }
    #pragma unroll
    for (int oi = 0; oi < 8; oi++)
        #pragma unroll
        for (int j = 0; j < 4; j++)
            out[(size_t)(b * 64 + ocb + oi) * P_ + p0 + lane + j * 32] = acc[j][oi];
}

// ---------------- launch ---------------------------------------------------
extern "C" void kernel_launch(void* const* d_in, const int* in_sizes, int n_in,
                              void* d_out, int out_size) {
    const float* inp    = (const float*)d_in[0];
    const float* W_in   = (const float*)d_in[1];
    const float* W_dw   = (const float*)d_in[2];
    const float* W_s    = (const float*)d_in[3];
    const float* W_t1   = (const float*)d_in[4];
    const float* W_t2   = (const float*)d_in[5];
    const float* m_in_w = (const float*)d_in[6];
    const float* m_cw   = (const float*)d_in[7];
    const float* m_cb   = (const float*)d_in[8];
    const float* m_x_w  = (const float*)d_in[9];
    const float* m_dt_w = (const float*)d_in[10];
    const float* m_dt_b = (const float*)d_in[11];
    const float* m_Alog = (const float*)d_in[12];
    const float* m_D    = (const float*)d_in[13];
    const float* m_ow   = (const float*)d_in[14];
    const float* W_out  = (const float*)d_in[15];

    cudaFuncSetAttribute(k_pw,    cudaFuncAttributeMaxDynamicSharedMemorySize, 98304);
    cudaFuncSetAttribute(k_conv,  cudaFuncAttributeMaxDynamicSharedMemorySize, CONV_SM);
    cudaFuncSetAttribute(k_mamba, cudaFuncAttributeMaxDynamicSharedMemorySize, 168960);
    cudaFuncSetAttribute(k_out,   cudaFuncAttributeMaxDynamicSharedMemorySize, 98304);

    k_wt<<<(54 * 8192 + 255) / 256, 256>>>(W_s);
    k_pw<<<dim3(P_ / 128, 2), 256, 98304>>>(inp, W_in);
    k_dw<<<512, 256>>>(W_dw);
    k_conv<<<dim3(14, D_, 2), CTH, CONV_SM>>>();
    k_mamba<<<2, 256, 168960>>>(W_t1, m_in_w, m_cw, m_cb, m_x_w, m_dt_w, m_dt_b,
                                m_Alog, m_D, m_ow, W_t2);
    k_out<<<dim3(P_ / 128, 2), 256, 98304>>>(W_out, (float*)d_out);
}

// round 17
// speedup vs baseline: 2.0476x; 1.0180x over previous
#include <cuda_runtime.h>
#include <math.h>
#include <cstdint>

#define D_     32
#define H_     56
#define W_     56
#define HW     3136        // 56*56
#define P_     100352      // 32*56*56
#define NST    16
#define L_     32

// ======================= helpers ===========================================
__device__ __forceinline__ uint32_t smem_u32(const void* p) {
    uint32_t a;
    asm("{ .reg .u64 t; cvta.to.shared.u64 t, %1; cvt.u32.u64 %0, t; }"
        : "=r"(a) : "l"(p));
    return a;
}
__device__ __forceinline__ float to_tf32(float x) {
    uint32_t r;
    asm("cvt.rna.tf32.f32 %0, %1;" : "=r"(r) : "f"(x));
    return __uint_as_float(r);
}
__device__ __forceinline__ void cpasync16(uint32_t smaddr, const void* g) {
    asm volatile("cp.async.ca.shared.global [%0], [%1], 16;"
                 :: "r"(smaddr), "l"(g) : "memory");
}
#define CP_COMMIT() asm volatile("cp.async.commit_group;" ::: "memory")
#define CP_WAIT0()  asm volatile("cp.async.wait_group 0;" ::: "memory")

// m16n8k8 tf32 mma (compute_103-legal; no tcgen05)
__device__ __forceinline__ void mma1688(float* d, const uint32_t* a,
                                        uint32_t b0, uint32_t b1) {
    asm volatile(
        "mma.sync.aligned.m16n8k8.row.col.f32.tf32.tf32.f32 "
        "{%0,%1,%2,%3}, {%4,%5,%6,%7}, {%8,%9}, {%0,%1,%2,%3};"
        : "+f"(d[0]), "+f"(d[1]), "+f"(d[2]), "+f"(d[3])
        : "r"(a[0]), "r"(a[1]), "r"(a[2]), "r"(a[3]), "r"(b0), "r"(b1));
}

// f32x2 helpers (k_pw)
__device__ __forceinline__ void fma2(unsigned long long& d,
                                     unsigned long long a,
                                     unsigned long long b) {
    asm("fma.rn.f32x2 %0, %1, %2, %0;" : "+l"(d) : "l"(a), "l"(b));
}
__device__ __forceinline__ unsigned long long dup2(float x) {
    unsigned long long r;
    asm("mov.b64 %0, {%1, %1};" : "=l"(r) : "f"(x));
    return r;
}
__device__ __forceinline__ float2 unpk(unsigned long long v) {
    float2 f;
    asm("mov.b64 {%0, %1}, %2;" : "=f"(f.x), "=f"(f.y) : "l"(v));
    return f;
}

// ======================= scratch ===========================================
__device__ float g_x   [2 * 256 * P_];
__device__ float g_xc  [2 * 256 * P_];
__device__ float g_x1r [2 * 128 * P_];
__device__ __align__(16) float g_wt[54 * 8704];  // tf32 weights [ch*27+tap][c*136+o]
__device__ float g_t0  [2 * 128 * L_];
__device__ float g_gate[2 * 128 * L_];

// ---------------- K0: weight prep: tf32, per c-half, padded stride 136 -----
__global__ void k_wt(const float* __restrict__ Ws) {
    int i = blockIdx.x * 256 + threadIdx.x;
    if (i >= 54 * 8192) return;
    int cht = i / 8192;            // ch*27 + tap
    int r   = i % 8192;
    int c   = r / 128;             // 0..63 within half
    int o   = r % 128;
    int ch  = cht / 27, tap = cht % 27;
    g_wt[cht * 8704 + c * 136 + o] = to_tf32(Ws[(o * 128 + ch * 64 + c) * 27 + tap]);
}

// ---------------- K1: pointwise conv 64 -> 256 (f32x2) ---------------------
__global__ void __launch_bounds__(256) k_pw(const float* __restrict__ inp,
                                            const float* __restrict__ Win) {
    extern __shared__ float sm[];
    float* Wsh = sm;            // 16384: [c*256 + o]
    float* Ish = sm + 16384;    //  8192: [c*128 + p]
    int b  = blockIdx.y;
    int p0 = blockIdx.x * 128;
    int tid = threadIdx.x;
    for (int i = tid; i < 16384; i += 256) {
        int o = i >> 6, c = i & 63;
        Wsh[c * 256 + o] = Win[i];
    }
    for (int i = tid; i < 8192; i += 256) {
        int c = i >> 7, p = i & 127;
        Ish[i] = inp[(size_t)(b * 64 + c) * P_ + p0 + p];
    }
    __syncthreads();
    int p  = tid & 127;
    int oh = tid >> 7;
    size_t base = (size_t)(b * 256) * P_ + p0 + p;
    for (int oc = 0; oc < 8; oc++) {
        int ob = oh * 128 + oc * 16;
        unsigned long long acc[8];
        #pragma unroll
        for (int j = 0; j < 8; j++) acc[j] = 0ull;
        #pragma unroll 8
        for (int c = 0; c < 64; c++) {
            unsigned long long xx = dup2(Ish[c * 128 + p]);
            const ulonglong2* wp = (const ulonglong2*)&Wsh[c * 256 + ob];
            ulonglong2 w0 = wp[0], w1 = wp[1], w2 = wp[2], w3 = wp[3];
            fma2(acc[0], w0.x, xx); fma2(acc[1], w0.y, xx);
            fma2(acc[2], w1.x, xx); fma2(acc[3], w1.y, xx);
            fma2(acc[4], w2.x, xx); fma2(acc[5], w2.y, xx);
            fma2(acc[6], w3.x, xx); fma2(acc[7], w3.y, xx);
        }
        #pragma unroll
        for (int j = 0; j < 8; j++) {
            float2 f = unpk(acc[j]);
            g_x[base + (size_t)(ob + 2 * j)     * P_] = f.x;
            g_x[base + (size_t)(ob + 2 * j + 1) * P_] = f.y;
        }
    }
}

// ---------------- K2: depthwise 3x3x3 + fused pool, d-chunked --------------
// grid (512, 4): block = (b,c) x d-chunk of 8. Rolling 3-plane smem buffer.
__global__ void __launch_bounds__(256) k_dw(const float* __restrict__ Wdw) {
    __shared__ float buf[3][HW];
    __shared__ float red[8];
    int blk = blockIdx.x;
    int b = blk >> 8, c = blk & 255;
    int dlo = blockIdx.y * 8;
    int dhi = dlo + 8;
    int tid = threadIdx.x;
    int lane = tid & 31, wid = tid >> 5;
    float wreg[27];
    #pragma unroll
    for (int t = 0; t < 27; t++) wreg[t] = Wdw[c * 27 + t];
    const float* src = &g_x [(size_t)(b * 256 + c) * P_];
    float*       dst = &g_xc[(size_t)(b * 256 + c) * P_];
    bool pool = (c >= 128);

    // preload plane dlo (and dlo-1 if it exists)
    {
        const float* p0s = &src[dlo * HW];
        float* b0 = buf[dlo % 3];
        for (int i = tid; i < HW; i += 256) b0[i] = p0s[i];
        if (dlo > 0) {
            const float* pm = &src[(dlo - 1) * HW];
            float* bm = buf[(dlo + 2) % 3];
            for (int i = tid; i < HW; i += 256) bm[i] = pm[i];
        }
    }

    for (int d = dlo; d < dhi; d++) {
        __syncthreads();
        if (d + 1 < D_) {
            float* nb = buf[(d + 1) % 3];
            const float* np = &src[(d + 1) * HW];
            for (int i = tid; i < HW; i += 256) nb[i] = np[i];
        }
        __syncthreads();
        const float* pm1 = (d > 0)      ? buf[(d + 2) % 3] : nullptr;
        const float* p0  =                buf[d % 3];
        const float* pp1 = (d + 1 < D_) ? buf[(d + 1) % 3] : nullptr;
        const float* pl[3] = {pm1, p0, pp1};
        float psum = 0.f;
        for (int i = tid; i < HW; i += 256) {
            int h = i / 56, w = i % 56;
            float acc = 0.f;
            #pragma unroll
            for (int kd = 0; kd < 3; kd++) {
                const float* pn = pl[kd];
                if (!pn) continue;
                #pragma unroll
                for (int kh = 0; kh < 3; kh++) {
                    int hh = h + kh - 1;
                    if ((unsigned)hh >= 56u) continue;
                    const float* row = &pn[hh * 56];
                    #pragma unroll
                    for (int kw = 0; kw < 3; kw++) {
                        int ww = w + kw - 1;
                        if ((unsigned)ww < 56u)
                            acc += wreg[kd * 9 + kh * 3 + kw] * row[ww];
                    }
                }
            }
            dst[d * HW + i] = acc;
            psum += acc;
        }
        if (pool) {
            #pragma unroll
            for (int off = 16; off; off >>= 1)
                psum += __shfl_down_sync(0xffffffffu, psum, off);
            if (lane == 0) red[wid] = psum;
            __syncthreads();
            if (tid == 0) {
                float s = 0.f;
                #pragma unroll
                for (int j = 0; j < 8; j++) s += red[j];
                g_t0[(b * 128 + (c - 128)) * L_ + d] = s * (1.f / 3136.f);
            }
        }
    }
}

// ---------------- K3: dense 3x3x3 conv 128->128 via mma.sync tf32 ----------
// Block = (b, d, 4 h-rows), 512 thr / 16 warps. M=128 o, N=224 px, K=128c*27.
// Warp: og4 = wid&3 -> 32 o (2 m16 tiles), hh = wid>>2 -> one h-row (7 n8).
#define WP_    72                 // padded Ish row (bank-conflict-free B frags)
#define CHALF  64
#define ISH_F  (6 * CHALF * WP_)  // 27648 floats
#define WSH_F  8704               // 64*136 (bank-conflict-free A frags)
#define CONV_SM ((ISH_F + 2 * WSH_F) * 4)   // 180224 B
#define CTH    512

__global__ void __launch_bounds__(CTH, 1) k_conv() {
    extern __shared__ float sm[];
    float* Ish  = sm;
    float* Wsh0 = sm + ISH_F;
    float* Wsh1 = sm + ISH_F + WSH_F;
    int b  = blockIdx.z;
    int d  = blockIdx.y;
    int h0 = blockIdx.x * 4;
    int tid = threadIdx.x;
    int wid = tid >> 5, lane = tid & 31;
    int lr = lane >> 2, lc = lane & 3;
    int og4 = wid & 3, hh = wid >> 2;

    int dds[3]; int nkd = 0;
    #pragma unroll
    for (int kd = 0; kd < 3; kd++) {
        int dd = d + kd - 1;
        if (dd >= 0 && dd < D_) dds[nkd++] = dd;
    }
    int tapsPer = nkd * 9;
    int ntap = 2 * tapsPer;

    float acc[2][7][4];
    #pragma unroll
    for (int m = 0; m < 2; m++)
        #pragma unroll
        for (int j = 0; j < 7; j++)
            #pragma unroll
            for (int r = 0; r < 4; r++) acc[m][j][r] = 0.f;

    // prefetch tap 0 weights
    {
        const float* g = &g_wt[((dds[0] - (d - 1)) * 9) * 8704];
        uint32_t sa = smem_u32(Wsh0);
        for (int i = tid; i < WSH_F / 4; i += CTH)
            cpasync16(sa + i * 16, (const char*)g + i * 16);
        CP_COMMIT();
    }

    for (int T = 0; T < ntap; T++) {
        CP_WAIT0();
        __syncthreads();
        if (T + 1 < ntap) {
            int Tn = T + 1;
            int chn = Tn / tapsPer, rn = Tn % tapsPer;
            int kdin = rn / 9, t9n = rn % 9;
            const float* g = &g_wt[(chn * 27 + (dds[kdin] - (d - 1)) * 9 + t9n) * 8704];
            uint32_t sa = smem_u32(((Tn & 1) ? Wsh1 : Wsh0));
            for (int i = tid; i < WSH_F / 4; i += CTH)
                cpasync16(sa + i * 16, (const char*)g + i * 16);
            CP_COMMIT();
        }
        int ch = T / tapsPer, r2 = T % tapsPer;
        int kdi = r2 / 9, t9 = r2 % 9, kh = t9 / 3, kw = t9 % 3;
        if (t9 == 0) {   // new (ch, kd) plane -> refill Ish
            const float* src = &g_xc[((size_t)(b * 256 + ch * 64) * D_ + dds[kdi]) * HW];
            for (int i = tid; i < 6 * CHALF * 58; i += CTH) {
                int r   = i / (CHALF * 58);
                int rem = i % (CHALF * 58);
                int c   = rem / 58;
                int wp  = rem % 58;
                int ih  = h0 + r - 1;
                int w   = wp - 1;
                float v = 0.f;
                if ((unsigned)ih < 56u && (unsigned)w < 56u)
                    v = to_tf32(src[(size_t)c * (D_ * HW) + ih * 56 + w]);
                Ish[(r * CHALF + c) * WP_ + wp] = v;
            }
            __syncthreads();
        }
        const float* Wb = (T & 1) ? Wsh1 : Wsh0;
        const float* AB = &Wb[lc * 136 + og4 * 32 + lr];
        const float* BB = &Ish[((hh + kh) * CHALF + lc) * WP_ + lr + kw];
        #pragma unroll
        for (int ks = 0; ks < 8; ks++) {
            uint32_t a[2][4];
            const float* Ab = AB + ks * 8 * 136;
            #pragma unroll
            for (int mt = 0; mt < 2; mt++) {
                const float* p = Ab + mt * 16;
                a[mt][0] = __float_as_uint(p[0]);
                a[mt][1] = __float_as_uint(p[8]);
                a[mt][2] = __float_as_uint(p[544]);
                a[mt][3] = __float_as_uint(p[552]);
            }
            const float* Bb = BB + ks * 8 * WP_;
            #pragma unroll
            for (int j = 0; j < 7; j++) {
                uint32_t b0 = __float_as_uint(Bb[j * 8]);
                uint32_t b1 = __float_as_uint(Bb[j * 8 + 4 * WP_]);
                #pragma unroll
                for (int mt = 0; mt < 2; mt++)
                    mma1688(acc[mt][j], a[mt], b0, b1);
            }
        }
    }
    // ---- epilogue: relu, stage (coalesce), store --------------------------
    __syncthreads();
    float* stage = sm;     // [o][228] = 29184 floats (116.7KB < 176KB)
    #pragma unroll
    for (int mt = 0; mt < 2; mt++) {
        int o = og4 * 32 + mt * 16 + lr;
        #pragma unroll
        for (int j = 0; j < 7; j++) {
            int n = hh * 56 + j * 8 + lc * 2;
            stage[o * 228 + n]           = fmaxf(acc[mt][j][0], 0.f);
            stage[o * 228 + n + 1]       = fmaxf(acc[mt][j][1], 0.f);
            stage[(o + 8) * 228 + n]     = fmaxf(acc[mt][j][2], 0.f);
            stage[(o + 8) * 228 + n + 1] = fmaxf(acc[mt][j][3], 0.f);
        }
    }
    __syncthreads();
    for (int i = tid; i < 128 * 224; i += CTH) {
        int o   = i / 224;
        int rem = i % 224;
        int h2  = rem / 56;
        int w   = rem % 56;
        g_x1r[((size_t)(b * 128 + o) * D_ + d) * HW + (h0 + h2) * 56 + w] =
            stage[o * 228 + h2 * 56 + w];
    }
}

// ---------------- K6: W_t1 + full Mamba + W_t2 + sigmoid (512 thr) ---------
#define MTH 512
__global__ void __launch_bounds__(MTH) k_mamba(
        const float* __restrict__ Wt1,   const float* __restrict__ min_w,
        const float* __restrict__ cw,    const float* __restrict__ cb,
        const float* __restrict__ mx_w,  const float* __restrict__ mdt_w,
        const float* __restrict__ mdt_b, const float* __restrict__ A_log,
        const float* __restrict__ Dp,    const float* __restrict__ mout_w,
        const float* __restrict__ Wt2) {
    extern __shared__ float sm[];
    float* t0s = sm;           // 4096
    float* seq = sm + 4096;    // 4096
    float* xb  = sm + 8192;    // 8192
    float* zb  = sm + 16384;   // 8192
    float* xcv = sm + 24576;   // 8192
    float* dtb = sm + 32768;   // 8192
    float* prb = sm + 40960;   // 1280
    int b = blockIdx.x, tid = threadIdx.x;

    for (int i = tid; i < 4096; i += MTH) t0s[i] = g_t0[b * 4096 + i];
    __syncthreads();
    for (int i = tid; i < 4096; i += MTH) {
        int l = i >> 7, h = i & 127;
        float a = 0.f;
        for (int c = 0; c < 128; c++) a += Wt1[h * 128 + c] * t0s[c * L_ + l];
        seq[i] = a;
    }
    __syncthreads();
    for (int i = tid; i < 16384; i += MTH) {
        int l = i >> 9, j = i & 511;
        float a = 0.f;
        const float* wr = &min_w[j * 128];
        for (int h = 0; h < 128; h++) a += wr[h] * seq[l * 128 + h];
        if (j < 256) xb[l * 256 + j] = a;
        else         zb[l * 256 + (j - 256)] = a;
    }
    __syncthreads();
    for (int i = tid; i < 8192; i += MTH) {
        int l = i >> 8, dch = i & 255;
        float a = cb[dch];
        #pragma unroll
        for (int k = 0; k < 4; k++) {
            int ll = l - 3 + k;
            if (ll >= 0) a += xb[ll * 256 + dch] * cw[dch * 4 + k];
        }
        xcv[i] = a / (1.f + expf(-a));
    }
    __syncthreads();
    for (int i = tid; i < 1280; i += MTH) {
        int l = i / 40, j = i % 40;
        float a = 0.f;
        const float* wr = &mx_w[j * 256];
        for (int dd = 0; dd < 256; dd++) a += wr[dd] * xcv[l * 256 + dd];
        prb[i] = a;
    }
    __syncthreads();
    for (int i = tid; i < 8192; i += MTH) {
        int l = i >> 8, dch = i & 255;
        float a = mdt_b[dch];
        const float* wr = &mdt_w[dch * 8];
        #pragma unroll
        for (int r = 0; r < 8; r++) a += wr[r] * prb[l * 40 + r];
        dtb[i] = (a > 20.f) ? a : log1pf(expf(a));
    }
    __syncthreads();
    if (tid < 256) {
        int dch = tid;
        float A[NST], hst[NST];
        #pragma unroll
        for (int n = 0; n < NST; n++) {
            A[n]   = -expf(A_log[dch * NST + n]);
            hst[n] = 0.f;
        }
        float Dv = Dp[dch];
        for (int l = 0; l < L_; l++) {
            float dtv = dtb[l * 256 + dch];
            float xv  = xcv[l * 256 + dch];
            float y = 0.f;
            #pragma unroll
            for (int n = 0; n < NST; n++) {
                float dA = __expf(dtv * A[n]);
                hst[n] = dA * hst[n] + dtv * prb[l * 40 + 8 + n] * xv;
                y += hst[n] * prb[l * 40 + 24 + n];
            }
            y += xv * Dv;
            float zv = zb[l * 256 + dch];
            xb[l * 256 + dch] = y * (zv / (1.f + expf(-zv)));
        }
    }
    __syncthreads();
    for (int i = tid; i < 4096; i += MTH) {
        int l = i >> 7, h = i & 127;
        float a = 0.f;
        const float* wr = &mout_w[h * 256];
        for (int dd = 0; dd < 256; dd++) a += wr[dd] * xb[l * 256 + dd];
        dtb[i] = a;
    }
    __syncthreads();
    for (int i = tid; i < 4096; i += MTH) {
        int o = i >> 5, l = i & 31;
        float a = 0.f;
        const float* wr = &Wt2[o * 128];
        for (int c = 0; c < 128; c++) a += wr[c] * dtb[l * 128 + c];
        g_gate[b * 4096 + o * L_ + l] = 1.f / (1.f + expf(-a));
    }
}

// ---------------- K7: out = W_out @ (x1r * gate) ---------------------------
__global__ void __launch_bounds__(256) k_out(const float* __restrict__ Wout,
                                             float* __restrict__ out) {
    extern __shared__ float sm[];
    float* Xsh = sm;           // 16384: [c*128 + p]
    float* Wsh = sm + 16384;   //  8192: [c*64 + o]
    int b  = blockIdx.y;
    int p0 = blockIdx.x * 128;
    int tid = threadIdx.x;
    for (int i = tid; i < 8192; i += 256) {
        int o = i >> 7, c = i & 127;
        Wsh[c * 64 + o] = Wout[i];
    }
    for (int i = tid; i < 16384; i += 256) {
        int c = i >> 7, p = i & 127;
        int gp = p0 + p;
        int d  = gp / HW;
        Xsh[i] = g_x1r[(size_t)(b * 128 + c) * P_ + gp] *
                 g_gate[b * 4096 + c * L_ + d];
    }
    __syncthreads();
    int lane = tid & 31;
    int ocb  = (tid >> 5) * 8;
    float acc[4][8];
    #pragma unroll
    for (int j = 0; j < 4; j++)
        #pragma unroll
        for (int oi = 0; oi < 8; oi++) acc[j][oi] = 0.f;
    #pragma unroll 4
    for (int c = 0; c < 128; c++) {
        float xv[4];
        #pragma unroll
        for (int j = 0; j < 4; j++) xv[j] = Xsh[c * 128 + lane + j * 32];
        float4 wa = *(const float4*)&Wsh[c * 64 + ocb];
        float4 wb2 = *(const float4*)&Wsh[c * 64 + ocb + 4];
        float wv[8] = {wa.x, wa.y, wa.z, wa.w, wb2.x, wb2.y, wb2.z, wb2.w};
        #pragma unroll
        for (int j = 0; j < 4; j++)
            #pragma unroll
            for (int oi = 0; oi < 8; oi++)
                acc[j][oi] += wv[oi] * xv[j];
    }
    #pragma unroll
    for (int oi = 0; oi < 8; oi++)
        #pragma unroll
        for (int j = 0; j < 4; j++)
            out[(size_t)(b * 64 + ocb + oi) * P_ + p0 + lane + j * 32] = acc[j][oi];
}

// ---------------- launch ---------------------------------------------------
extern "C" void kernel_launch(void* const* d_in, const int* in_sizes, int n_in,
                              void* d_out, int out_size) {
    const float* inp    = (const float*)d_in[0];
    const float* W_in   = (const float*)d_in[1];
    const float* W_dw   = (const float*)d_in[2];
    const float* W_s    = (const float*)d_in[3];
    const float* W_t1   = (const float*)d_in[4];
    const float* W_t2   = (const float*)d_in[5];
    const float* m_in_w = (const float*)d_in[6];
    const float* m_cw   = (const float*)d_in[7];
    const float* m_cb   = (const float*)d_in[8];
    const float* m_x_w  = (const float*)d_in[9];
    const float* m_dt_w = (const float*)d_in[10];
    const float* m_dt_b = (const float*)d_in[11];
    const float* m_Alog = (const float*)d_in[12];
    const float* m_D    = (const float*)d_in[13];
    const float* m_ow   = (const float*)d_in[14];
    const float* W_out  = (const float*)d_in[15];

    cudaFuncSetAttribute(k_pw,    cudaFuncAttributeMaxDynamicSharedMemorySize, 98304);
    cudaFuncSetAttribute(k_conv,  cudaFuncAttributeMaxDynamicSharedMemorySize, CONV_SM);
    cudaFuncSetAttribute(k_mamba, cudaFuncAttributeMaxDynamicSharedMemorySize, 168960);
    cudaFuncSetAttribute(k_out,   cudaFuncAttributeMaxDynamicSharedMemorySize, 98304);

    k_wt<<<(54 * 8192 + 255) / 256, 256>>>(W_s);
    k_pw<<<dim3(P_ / 128, 2), 256, 98304>>>(inp, W_in);
    k_dw<<<dim3(512, 4), 256>>>(W_dw);
    k_conv<<<dim3(14, D_, 2), CTH, CONV_SM>>>();
    k_mamba<<<2, MTH, 168960>>>(W_t1, m_in_w, m_cw, m_cb, m_x_w, m_dt_w, m_dt_b,
                                m_Alog, m_D, m_ow, W_t2);
    k_out<<<dim3(P_ / 128, 2), 256, 98304>>>(W_out, (float*)d_out);
}